// round 2
// baseline (speedup 1.0000x reference)
#include <cuda_runtime.h>
#include <cstddef>

#define NNODES 100000
#define MAXE   1600000

// ---------------- scratch (static device globals; no allocations) ----------------
__device__ __align__(16) float g_bufA[(size_t)NNODES * 128];
__device__ __align__(16) float g_bufB[(size_t)NNODES * 128];
__device__ int   g_cnt[NNODES];
__device__ int   g_wp[NNODES];
__device__ int   g_row_ptr[NNODES + 1];
__device__ int   g_col[MAXE];
__device__ int   g_rowe[MAXE];
__device__ int   g_cole[MAXE];
__device__ float g_invdeg[NNODES];
__device__ __align__(16) float g_stats[256];   // [sum[128], sumsq[128]]
__device__ __align__(16) float g_ss[256];      // [scale[128], shift[128]]
__device__ int   g_is64;

// ---------------- dtype detection + edge extraction ----------------
// int64 node ids < 2^31: every odd 32-bit word is 0. int32 data: odd words are
// random ids in [0,100000) -> essentially never all zero over 2048 samples.
__global__ void k_detect(const unsigned int* __restrict__ w) {
    if (threadIdx.x == 0 && blockIdx.x == 0) g_is64 = 1;
    __syncthreads();
    int i = blockIdx.x * blockDim.x + threadIdx.x;
    if (i < 2048) {
        if (w[2 * i + 1] != 0u) g_is64 = 0;   // benign race: only writes 0
    }
}

__global__ void k_zero_cnt() {
    int i = blockIdx.x * blockDim.x + threadIdx.x;
    if (i < NNODES) g_cnt[i] = 0;
}

// extract row/col as int (either dtype) + histogram rows
__global__ void k_extract(const void* __restrict__ ei, int E) {
    int is64 = g_is64;
    int i = blockIdx.x * blockDim.x + threadIdx.x;
    int stride = gridDim.x * blockDim.x;
    if (is64) {
        const long long* p = (const long long*)ei;
        for (; i < E; i += stride) {
            int r = (int)p[i];
            int c = (int)p[E + i];
            g_rowe[i] = r; g_cole[i] = c;
            atomicAdd(&g_cnt[r], 1);
        }
    } else {
        const int* p = (const int*)ei;
        for (; i < E; i += stride) {
            int r = p[i];
            int c = p[E + i];
            g_rowe[i] = r; g_cole[i] = c;
            atomicAdd(&g_cnt[r], 1);
        }
    }
}

// single-block scan over NNODES counts -> row_ptr, write-pointers, invdeg
__global__ void k_scan() {
    __shared__ int wsum[32];
    __shared__ int carry;
    int tid = threadIdx.x, lane = tid & 31, w = tid >> 5;
    if (tid == 0) { carry = 0; g_row_ptr[0] = 0; }
    __syncthreads();
    for (int base = 0; base < NNODES; base += 1024) {
        int i = base + tid;
        int v = (i < NNODES) ? g_cnt[i] : 0;
        int s = v;
        #pragma unroll
        for (int o = 1; o < 32; o <<= 1) {
            int t = __shfl_up_sync(0xffffffffu, s, o);
            if (lane >= o) s += t;
        }
        if (lane == 31) wsum[w] = s;
        __syncthreads();
        if (w == 0) {
            int x = wsum[lane];
            int ss = x;
            #pragma unroll
            for (int o = 1; o < 32; o <<= 1) {
                int t = __shfl_up_sync(0xffffffffu, ss, o);
                if (lane >= o) ss += t;
            }
            wsum[lane] = ss - x;   // exclusive
        }
        __syncthreads();
        int incl = s + wsum[w] + carry;
        if (i < NNODES) {
            g_row_ptr[i + 1] = incl;
            g_wp[i] = incl - v;
            g_invdeg[i] = 1.0f / ((float)v + 1e-6f);
        }
        __syncthreads();
        if (tid == 1023) carry = incl;
        __syncthreads();
    }
}

__global__ void k_fill(int E) {
    int i = blockIdx.x * blockDim.x + threadIdx.x;
    int stride = gridDim.x * blockDim.x;
    for (; i < E; i += stride) {
        int r = g_rowe[i];
        int p = atomicAdd(&g_wp[r], 1);
        g_col[p] = g_cole[i];
    }
}

// ---------------- aggregation kernels (warp per node) ----------------
__global__ void k_agg64(const float* __restrict__ src, float* __restrict__ dst) {
    int gw = (blockIdx.x * blockDim.x + threadIdx.x) >> 5;
    if (gw >= NNODES) return;
    int lane = threadIdx.x & 31;
    int beg = g_row_ptr[gw], end = g_row_ptr[gw + 1];
    float2 a0 = {0.f, 0.f}, a1 = {0.f, 0.f};
    const float2* s2 = (const float2*)src;
    int e = beg;
    for (; e + 1 < end; e += 2) {
        int c0 = g_col[e], c1 = g_col[e + 1];
        float2 v0 = __ldg(s2 + (size_t)c0 * 32 + lane);
        float2 v1 = __ldg(s2 + (size_t)c1 * 32 + lane);
        a0.x += v0.x; a0.y += v0.y;
        a1.x += v1.x; a1.y += v1.y;
    }
    if (e < end) {
        int c0 = g_col[e];
        float2 v0 = __ldg(s2 + (size_t)c0 * 32 + lane);
        a0.x += v0.x; a0.y += v0.y;
    }
    float w = g_invdeg[gw];
    float2 r;
    r.x = (a0.x + a1.x) * w;
    r.y = (a0.y + a1.y) * w;
    ((float2*)dst)[(size_t)gw * 32 + lane] = r;
}

// gather h1 [N,128], apply BN(scale/shift)+relu on the fly, aggregate
__global__ void k_agg128_bn(const float* __restrict__ src, float* __restrict__ dst) {
    int gw = (blockIdx.x * blockDim.x + threadIdx.x) >> 5;
    if (gw >= NNODES) return;
    int lane = threadIdx.x & 31;
    float4 sc = *(const float4*)&g_ss[lane * 4];
    float4 sh = *(const float4*)&g_ss[128 + lane * 4];
    int beg = g_row_ptr[gw], end = g_row_ptr[gw + 1];
    float4 a0 = {0.f, 0.f, 0.f, 0.f}, a1 = {0.f, 0.f, 0.f, 0.f};
    const float4* s4 = (const float4*)src;
    int e = beg;
    for (; e + 1 < end; e += 2) {
        int c0 = g_col[e], c1 = g_col[e + 1];
        float4 v0 = __ldg(s4 + (size_t)c0 * 32 + lane);
        float4 v1 = __ldg(s4 + (size_t)c1 * 32 + lane);
        a0.x += fmaxf(fmaf(v0.x, sc.x, sh.x), 0.f);
        a0.y += fmaxf(fmaf(v0.y, sc.y, sh.y), 0.f);
        a0.z += fmaxf(fmaf(v0.z, sc.z, sh.z), 0.f);
        a0.w += fmaxf(fmaf(v0.w, sc.w, sh.w), 0.f);
        a1.x += fmaxf(fmaf(v1.x, sc.x, sh.x), 0.f);
        a1.y += fmaxf(fmaf(v1.y, sc.y, sh.y), 0.f);
        a1.z += fmaxf(fmaf(v1.z, sc.z, sh.z), 0.f);
        a1.w += fmaxf(fmaf(v1.w, sc.w, sh.w), 0.f);
    }
    if (e < end) {
        int c0 = g_col[e];
        float4 v0 = __ldg(s4 + (size_t)c0 * 32 + lane);
        a0.x += fmaxf(fmaf(v0.x, sc.x, sh.x), 0.f);
        a0.y += fmaxf(fmaf(v0.y, sc.y, sh.y), 0.f);
        a0.z += fmaxf(fmaf(v0.z, sc.z, sh.z), 0.f);
        a0.w += fmaxf(fmaf(v0.w, sc.w, sh.w), 0.f);
    }
    float w = g_invdeg[gw];
    float4 r;
    r.x = (a0.x + a1.x) * w;
    r.y = (a0.y + a1.y) * w;
    r.z = (a0.z + a1.z) * w;
    r.w = (a0.w + a1.w) * w;
    ((float4*)dst)[(size_t)gw * 32 + lane] = r;
}

// final: aggregate t [N,64], add bias b3 -> d_out
__global__ void k_agg64_bias(const float* __restrict__ src,
                             const float* __restrict__ b3,
                             float* __restrict__ dst) {
    int gw = (blockIdx.x * blockDim.x + threadIdx.x) >> 5;
    if (gw >= NNODES) return;
    int lane = threadIdx.x & 31;
    float2 bb = __ldg((const float2*)b3 + lane);
    int beg = g_row_ptr[gw], end = g_row_ptr[gw + 1];
    float2 a0 = {0.f, 0.f}, a1 = {0.f, 0.f};
    const float2* s2 = (const float2*)src;
    int e = beg;
    for (; e + 1 < end; e += 2) {
        int c0 = g_col[e], c1 = g_col[e + 1];
        float2 v0 = __ldg(s2 + (size_t)c0 * 32 + lane);
        float2 v1 = __ldg(s2 + (size_t)c1 * 32 + lane);
        a0.x += v0.x; a0.y += v0.y;
        a1.x += v1.x; a1.y += v1.y;
    }
    if (e < end) {
        int c0 = g_col[e];
        float2 v0 = __ldg(s2 + (size_t)c0 * 32 + lane);
        a0.x += v0.x; a0.y += v0.y;
    }
    float w = g_invdeg[gw];
    float2 r;
    r.x = fmaf(a0.x + a1.x, w, bb.x);
    r.y = fmaf(a0.y + a1.y, w, bb.y);
    ((float2*)dst)[(size_t)gw * 32 + lane] = r;
}

// ---------------- GEMM: out[n][m] = sum_k A[n][k]*W[m][k] (+bias), opt BN+relu on A,
// opt per-column sum/sumsq accumulation into g_stats ----------------
template <int KD, int MD, int TN, bool BN_IN, bool STATS, bool BIAS>
__global__ void __launch_bounds__(256)
k_gemm(const float* __restrict__ A, const float* __restrict__ W,
       const float* __restrict__ bias, float* __restrict__ out, int nrows) {
    constexpr int KC = 16, BM = 128, TM = 8;
    __shared__ __align__(16) float As[BM][KC + 1];
    __shared__ __align__(16) float Ws[KC][MD];
    __shared__ float s_sum[128];
    __shared__ float s_sq[128];

    int tid = threadIdx.x;
    int tr = tid >> 4, tc = tid & 15;
    int row0 = blockIdx.x * BM;

    float acc[TM][TN];
    #pragma unroll
    for (int i = 0; i < TM; i++)
        #pragma unroll
        for (int j = 0; j < TN; j++) acc[i][j] = 0.f;

    if (STATS && tid < MD) { s_sum[tid] = 0.f; s_sq[tid] = 0.f; }

    for (int kc = 0; kc < KD; kc += KC) {
        __syncthreads();
        // A tile [128 x 16]
        for (int idx = tid; idx < BM * KC; idx += 256) {
            int k = idx & (KC - 1);
            int r = idx >> 4;
            int gr = row0 + r;
            float v = (gr < nrows) ? __ldg(&A[(size_t)gr * KD + kc + k]) : 0.f;
            if (BN_IN) {
                v = fmaxf(fmaf(v, __ldg(&g_ss[kc + k]), __ldg(&g_ss[128 + kc + k])), 0.f);
            }
            As[r][k] = v;
        }
        // W tile transposed: Ws[k][c] = W[c][kc+k]
        for (int idx = tid; idx < KC * MD; idx += 256) {
            int k = idx & (KC - 1);
            int c = idx >> 4;
            Ws[k][c] = __ldg(&W[(size_t)c * KD + kc + k]);
        }
        __syncthreads();

        #pragma unroll
        for (int k = 0; k < KC; k++) {
            float a[TM];
            #pragma unroll
            for (int i = 0; i < TM; i++) a[i] = As[tr * TM + i][k];
            float wv[TN];
            float4 w0 = *(const float4*)&Ws[k][tc * 4];
            wv[0] = w0.x; wv[1] = w0.y; wv[2] = w0.z; wv[3] = w0.w;
            if (TN == 8) {
                float4 w1 = *(const float4*)&Ws[k][64 + tc * 4];
                wv[4] = w1.x; wv[5] = w1.y; wv[6] = w1.z; wv[7] = w1.w;
            }
            #pragma unroll
            for (int i = 0; i < TM; i++)
                #pragma unroll
                for (int j = 0; j < TN; j++)
                    acc[i][j] = fmaf(a[i], wv[j], acc[i][j]);
        }
    }

    // epilogue
    float bj[TN];
    #pragma unroll
    for (int j = 0; j < TN; j++) {
        int c = (TN == 8) ? ((j < 4) ? tc * 4 + j : 64 + tc * 4 + (j - 4)) : tc * 4 + j;
        bj[j] = BIAS ? __ldg(&bias[c]) : 0.f;
    }

    float csum[TN], csq[TN];
    #pragma unroll
    for (int j = 0; j < TN; j++) { csum[j] = 0.f; csq[j] = 0.f; }

    #pragma unroll
    for (int i = 0; i < TM; i++) {
        int gr = row0 + tr * TM + i;
        if (gr < nrows) {
            float h[TN];
            #pragma unroll
            for (int j = 0; j < TN; j++) h[j] = acc[i][j] + bj[j];
            float4 o0 = {h[0], h[1], h[2], h[3]};
            *(float4*)&out[(size_t)gr * MD + tc * 4] = o0;
            if (TN == 8) {
                float4 o1 = {h[4], h[5], h[6], h[7]};
                *(float4*)&out[(size_t)gr * MD + 64 + tc * 4] = o1;
            }
            if (STATS) {
                #pragma unroll
                for (int j = 0; j < TN; j++) { csum[j] += h[j]; csq[j] += h[j] * h[j]; }
            }
        }
    }

    if (STATS) {
        __syncthreads();
        #pragma unroll
        for (int j = 0; j < TN; j++) {
            int c = (TN == 8) ? ((j < 4) ? tc * 4 + j : 64 + tc * 4 + (j - 4)) : tc * 4 + j;
            atomicAdd(&s_sum[c], csum[j]);
            atomicAdd(&s_sq[c], csq[j]);
        }
        __syncthreads();
        if (tid < MD) {
            atomicAdd(&g_stats[tid], s_sum[tid]);
            atomicAdd(&g_stats[128 + tid], s_sq[tid]);
        }
    }
}

__global__ void k_zero_stats() { g_stats[threadIdx.x] = 0.f; }

__global__ void k_bnfin(const float* __restrict__ gamma,
                        const float* __restrict__ beta, int MD) {
    int c = threadIdx.x;
    if (c < MD) {
        float s = g_stats[c], q = g_stats[128 + c];
        float mean = s * (1.0f / NNODES);
        float var = q * (1.0f / NNODES) - mean * mean;
        float sc = __ldg(&gamma[c]) * rsqrtf(var + 1e-5f);
        g_ss[c] = sc;
        g_ss[128 + c] = fmaf(-mean, sc, __ldg(&beta[c]));
    }
}

// ---------------- launch ----------------
extern "C" void kernel_launch(void* const* d_in, const int* in_sizes, int n_in,
                              void* d_out, int out_size) {
    const float* x   = (const float*)d_in[0];
    const void*  ei  = d_in[1];
    const float* W1  = (const float*)d_in[2];
    const float* b1  = (const float*)d_in[3];
    const float* ga1 = (const float*)d_in[4];
    const float* be1 = (const float*)d_in[5];
    const float* W2  = (const float*)d_in[6];
    const float* b2  = (const float*)d_in[7];
    const float* ga2 = (const float*)d_in[8];
    const float* be2 = (const float*)d_in[9];
    const float* W3  = (const float*)d_in[10];
    const float* b3  = (const float*)d_in[11];
    float* out = (float*)d_out;

    int E = in_sizes[1] / 2;
    if (E > MAXE) E = MAXE;

    float *bufA, *bufB;
    cudaGetSymbolAddress((void**)&bufA, g_bufA);
    cudaGetSymbolAddress((void**)&bufB, g_bufB);

    // dtype detect + CSR build
    k_detect<<<2, 1024>>>((const unsigned int*)ei);
    k_zero_cnt<<<(NNODES + 1023) / 1024, 1024>>>();
    k_extract<<<1024, 256>>>(ei, E);
    k_scan<<<1, 1024>>>();
    k_fill<<<1024, 256>>>(E);

    const int aggBlocks = (NNODES * 32 + 255) / 256;
    const int gemmBlocks = (NNODES + 127) / 128;

    // layer 1: agg(x) -> bufA[N,64]; GEMM1 (+b1, stats) -> bufB[N,128]
    k_agg64<<<aggBlocks, 256>>>(x, bufA);
    k_zero_stats<<<1, 256>>>();
    k_gemm<64, 128, 8, false, true, true><<<gemmBlocks, 256>>>(bufA, W1, b1, bufB, NNODES);
    k_bnfin<<<1, 128>>>(ga1, be1, 128);

    // layer 2: agg(relu(BN1(h1))) -> bufA[N,128]; GEMM2 (+b2, stats) -> bufB[N,128]
    k_agg128_bn<<<aggBlocks, 256>>>(bufB, bufA);
    k_zero_stats<<<1, 256>>>();
    k_gemm<128, 128, 8, false, true, true><<<gemmBlocks, 256>>>(bufA, W2, b2, bufB, NNODES);
    k_bnfin<<<1, 128>>>(ga2, be2, 128);

    // layer 3 (reordered): t = relu(BN2(h2)) @ W3^T -> bufA[N,64]; agg(t)+b3 -> out
    k_gemm<128, 64, 4, true, false, false><<<gemmBlocks, 256>>>(bufB, W3, nullptr, bufA, NNODES);
    k_agg64_bias<<<aggBlocks, 256>>>(bufA, b3, out);
}

// round 3
// speedup vs baseline: 1.1251x; 1.1251x over previous
#include <cuda_runtime.h>
#include <cstddef>

#define NNODES 100000
#define MAXE   1600000
#define SCAN_BLK 1024
#define SCAN_NB  ((NNODES + SCAN_BLK - 1) / SCAN_BLK)   // 98

// ---------------- scratch (static device globals; no allocations) ----------------
__device__ __align__(16) float g_bufA[(size_t)NNODES * 128];
__device__ __align__(16) float g_bufB[(size_t)NNODES * 128];
__device__ int   g_cnt[NNODES];
__device__ int   g_wp[NNODES];
__device__ int   g_row_ptr[NNODES + 1];
__device__ int   g_col[MAXE];
__device__ int   g_blk[SCAN_NB];
__device__ float g_invdeg[NNODES];
__device__ __align__(16) float g_stats[256];   // [sum[128], sumsq[128]]
__device__ __align__(16) float g_ss[256];      // [scale[128], shift[128]]
__device__ int   g_is64;

// ---------------- dtype detection ----------------
// int64 node ids < 2^31: every odd 32-bit word is 0. int32 data: odd words are
// random node ids -> essentially never all zero over 2048 samples.
__global__ void k_detect(const unsigned int* __restrict__ w) {
    if (threadIdx.x == 0 && blockIdx.x == 0) g_is64 = 1;
    __syncthreads();
    int i = blockIdx.x * blockDim.x + threadIdx.x;
    if (i < 2048) {
        if (w[2 * i + 1] != 0u) g_is64 = 0;   // benign race: only writes 0
    }
}

__global__ void k_zero_cnt() {
    int i = blockIdx.x * blockDim.x + threadIdx.x;
    if (i < NNODES) g_cnt[i] = 0;
}

// histogram of destination rows, reading edge_index directly (either dtype)
__global__ void k_hist(const void* __restrict__ ei, int E) {
    int is64 = g_is64;
    int i = blockIdx.x * blockDim.x + threadIdx.x;
    int stride = gridDim.x * blockDim.x;
    if (is64) {
        const long long* p = (const long long*)ei;
        for (; i < E; i += stride) atomicAdd(&g_cnt[(int)p[i]], 1);
    } else {
        const int* p = (const int*)ei;
        for (; i < E; i += stride) atomicAdd(&g_cnt[p[i]], 1);
    }
}

// ---------------- 3-phase parallel scan over g_cnt ----------------
// phase 1: per-block sums
__global__ void k_scan1() {
    __shared__ int wsum[32];
    int i = blockIdx.x * SCAN_BLK + threadIdx.x;
    int v = (i < NNODES) ? g_cnt[i] : 0;
    int lane = threadIdx.x & 31, w = threadIdx.x >> 5;
    #pragma unroll
    for (int o = 16; o > 0; o >>= 1) v += __shfl_down_sync(0xffffffffu, v, o);
    if (lane == 0) wsum[w] = v;
    __syncthreads();
    if (w == 0) {
        int s = wsum[lane];
        #pragma unroll
        for (int o = 16; o > 0; o >>= 1) s += __shfl_down_sync(0xffffffffu, s, o);
        if (lane == 0) g_blk[blockIdx.x] = s;
    }
}

// phase 2: exclusive scan of the SCAN_NB block sums (single block of 128)
__global__ void k_scan2() {
    __shared__ int wsum[4];
    int tid = threadIdx.x, lane = tid & 31, w = tid >> 5;
    int v = (tid < SCAN_NB) ? g_blk[tid] : 0;
    int s = v;
    #pragma unroll
    for (int o = 1; o < 32; o <<= 1) {
        int t = __shfl_up_sync(0xffffffffu, s, o);
        if (lane >= o) s += t;
    }
    if (lane == 31) wsum[w] = s;
    __syncthreads();
    int off = 0;
    #pragma unroll
    for (int j = 0; j < 4; j++) if (j < w) off += wsum[j];
    if (tid < SCAN_NB) g_blk[tid] = s - v + off;   // exclusive
}

// phase 3: per-block rescan + global offset; write row_ptr / wp / invdeg
__global__ void k_scan3() {
    __shared__ int wsum[32];
    int i = blockIdx.x * SCAN_BLK + threadIdx.x;
    int lane = threadIdx.x & 31, w = threadIdx.x >> 5;
    int v = (i < NNODES) ? g_cnt[i] : 0;
    int s = v;
    #pragma unroll
    for (int o = 1; o < 32; o <<= 1) {
        int t = __shfl_up_sync(0xffffffffu, s, o);
        if (lane >= o) s += t;
    }
    if (lane == 31) wsum[w] = s;
    __syncthreads();
    if (w == 0) {
        int x = wsum[lane];
        int ss = x;
        #pragma unroll
        for (int o = 1; o < 32; o <<= 1) {
            int t = __shfl_up_sync(0xffffffffu, ss, o);
            if (lane >= o) ss += t;
        }
        wsum[lane] = ss - x;
    }
    __syncthreads();
    int incl = s + wsum[w] + g_blk[blockIdx.x];
    if (i < NNODES) {
        g_row_ptr[i + 1] = incl;
        g_wp[i] = incl - v;
        g_invdeg[i] = 1.0f / ((float)v + 1e-6f);
        if (i == 0) g_row_ptr[0] = 0;
    }
}

// fill CSR columns, reading edge_index directly
__global__ void k_fill(const void* __restrict__ ei, int E) {
    int is64 = g_is64;
    int i = blockIdx.x * blockDim.x + threadIdx.x;
    int stride = gridDim.x * blockDim.x;
    if (is64) {
        const long long* p = (const long long*)ei;
        for (; i < E; i += stride) {
            int r = (int)p[i];
            int c = (int)p[E + i];
            int q = atomicAdd(&g_wp[r], 1);
            g_col[q] = c;
        }
    } else {
        const int* p = (const int*)ei;
        for (; i < E; i += stride) {
            int r = p[i];
            int c = p[E + i];
            int q = atomicAdd(&g_wp[r], 1);
            g_col[q] = c;
        }
    }
}

// ---------------- aggregation kernels (warp per node) ----------------
__global__ void k_agg64(const float* __restrict__ src, float* __restrict__ dst) {
    int gw = (blockIdx.x * blockDim.x + threadIdx.x) >> 5;
    if (gw >= NNODES) return;
    int lane = threadIdx.x & 31;
    int beg = g_row_ptr[gw], end = g_row_ptr[gw + 1];
    float2 a0 = {0.f, 0.f}, a1 = {0.f, 0.f};
    const float2* s2 = (const float2*)src;
    int e = beg;
    for (; e + 1 < end; e += 2) {
        int c0 = g_col[e], c1 = g_col[e + 1];
        float2 v0 = __ldg(s2 + (size_t)c0 * 32 + lane);
        float2 v1 = __ldg(s2 + (size_t)c1 * 32 + lane);
        a0.x += v0.x; a0.y += v0.y;
        a1.x += v1.x; a1.y += v1.y;
    }
    if (e < end) {
        int c0 = g_col[e];
        float2 v0 = __ldg(s2 + (size_t)c0 * 32 + lane);
        a0.x += v0.x; a0.y += v0.y;
    }
    float w = g_invdeg[gw];
    float2 r;
    r.x = (a0.x + a1.x) * w;
    r.y = (a0.y + a1.y) * w;
    ((float2*)dst)[(size_t)gw * 32 + lane] = r;
}

// gather h1 [N,128], apply BN(scale/shift)+relu on the fly, aggregate
__global__ void k_agg128_bn(const float* __restrict__ src, float* __restrict__ dst) {
    int gw = (blockIdx.x * blockDim.x + threadIdx.x) >> 5;
    if (gw >= NNODES) return;
    int lane = threadIdx.x & 31;
    float4 sc = *(const float4*)&g_ss[lane * 4];
    float4 sh = *(const float4*)&g_ss[128 + lane * 4];
    int beg = g_row_ptr[gw], end = g_row_ptr[gw + 1];
    float4 a0 = {0.f, 0.f, 0.f, 0.f}, a1 = {0.f, 0.f, 0.f, 0.f};
    const float4* s4 = (const float4*)src;
    int e = beg;
    for (; e + 1 < end; e += 2) {
        int c0 = g_col[e], c1 = g_col[e + 1];
        float4 v0 = __ldg(s4 + (size_t)c0 * 32 + lane);
        float4 v1 = __ldg(s4 + (size_t)c1 * 32 + lane);
        a0.x += fmaxf(fmaf(v0.x, sc.x, sh.x), 0.f);
        a0.y += fmaxf(fmaf(v0.y, sc.y, sh.y), 0.f);
        a0.z += fmaxf(fmaf(v0.z, sc.z, sh.z), 0.f);
        a0.w += fmaxf(fmaf(v0.w, sc.w, sh.w), 0.f);
        a1.x += fmaxf(fmaf(v1.x, sc.x, sh.x), 0.f);
        a1.y += fmaxf(fmaf(v1.y, sc.y, sh.y), 0.f);
        a1.z += fmaxf(fmaf(v1.z, sc.z, sh.z), 0.f);
        a1.w += fmaxf(fmaf(v1.w, sc.w, sh.w), 0.f);
    }
    if (e < end) {
        int c0 = g_col[e];
        float4 v0 = __ldg(s4 + (size_t)c0 * 32 + lane);
        a0.x += fmaxf(fmaf(v0.x, sc.x, sh.x), 0.f);
        a0.y += fmaxf(fmaf(v0.y, sc.y, sh.y), 0.f);
        a0.z += fmaxf(fmaf(v0.z, sc.z, sh.z), 0.f);
        a0.w += fmaxf(fmaf(v0.w, sc.w, sh.w), 0.f);
    }
    float w = g_invdeg[gw];
    float4 r;
    r.x = (a0.x + a1.x) * w;
    r.y = (a0.y + a1.y) * w;
    r.z = (a0.z + a1.z) * w;
    r.w = (a0.w + a1.w) * w;
    ((float4*)dst)[(size_t)gw * 32 + lane] = r;
}

// final: aggregate t [N,64], add bias b3 -> d_out
__global__ void k_agg64_bias(const float* __restrict__ src,
                             const float* __restrict__ b3,
                             float* __restrict__ dst) {
    int gw = (blockIdx.x * blockDim.x + threadIdx.x) >> 5;
    if (gw >= NNODES) return;
    int lane = threadIdx.x & 31;
    float2 bb = __ldg((const float2*)b3 + lane);
    int beg = g_row_ptr[gw], end = g_row_ptr[gw + 1];
    float2 a0 = {0.f, 0.f}, a1 = {0.f, 0.f};
    const float2* s2 = (const float2*)src;
    int e = beg;
    for (; e + 1 < end; e += 2) {
        int c0 = g_col[e], c1 = g_col[e + 1];
        float2 v0 = __ldg(s2 + (size_t)c0 * 32 + lane);
        float2 v1 = __ldg(s2 + (size_t)c1 * 32 + lane);
        a0.x += v0.x; a0.y += v0.y;
        a1.x += v1.x; a1.y += v1.y;
    }
    if (e < end) {
        int c0 = g_col[e];
        float2 v0 = __ldg(s2 + (size_t)c0 * 32 + lane);
        a0.x += v0.x; a0.y += v0.y;
    }
    float w = g_invdeg[gw];
    float2 r;
    r.x = fmaf(a0.x + a1.x, w, bb.x);
    r.y = fmaf(a0.y + a1.y, w, bb.y);
    ((float2*)dst)[(size_t)gw * 32 + lane] = r;
}

// ---------------- GEMM: out[n][m] = sum_k A[n][k]*W[m][k] (+bias), opt BN+relu on A,
// opt per-column sum/sumsq accumulation into g_stats ----------------
template <int KD, int MD, int TN, bool BN_IN, bool STATS, bool BIAS>
__global__ void __launch_bounds__(256)
k_gemm(const float* __restrict__ A, const float* __restrict__ W,
       const float* __restrict__ bias, float* __restrict__ out, int nrows) {
    constexpr int KC = 16, BM = 128, TM = 8;
    __shared__ __align__(16) float As[BM][KC + 1];
    __shared__ __align__(16) float Ws[KC][MD];
    __shared__ float s_sum[128];
    __shared__ float s_sq[128];

    int tid = threadIdx.x;
    int tr = tid >> 4, tc = tid & 15;
    int row0 = blockIdx.x * BM;

    float acc[TM][TN];
    #pragma unroll
    for (int i = 0; i < TM; i++)
        #pragma unroll
        for (int j = 0; j < TN; j++) acc[i][j] = 0.f;

    if (STATS && tid < MD) { s_sum[tid] = 0.f; s_sq[tid] = 0.f; }

    for (int kc = 0; kc < KD; kc += KC) {
        __syncthreads();
        for (int idx = tid; idx < BM * KC; idx += 256) {
            int k = idx & (KC - 1);
            int r = idx >> 4;
            int gr = row0 + r;
            float v = (gr < nrows) ? __ldg(&A[(size_t)gr * KD + kc + k]) : 0.f;
            if (BN_IN) {
                v = fmaxf(fmaf(v, __ldg(&g_ss[kc + k]), __ldg(&g_ss[128 + kc + k])), 0.f);
            }
            As[r][k] = v;
        }
        for (int idx = tid; idx < KC * MD; idx += 256) {
            int k = idx & (KC - 1);
            int c = idx >> 4;
            Ws[k][c] = __ldg(&W[(size_t)c * KD + kc + k]);
        }
        __syncthreads();

        #pragma unroll
        for (int k = 0; k < KC; k++) {
            float a[TM];
            #pragma unroll
            for (int i = 0; i < TM; i++) a[i] = As[tr * TM + i][k];
            float wv[TN];
            float4 w0 = *(const float4*)&Ws[k][tc * 4];
            wv[0] = w0.x; wv[1] = w0.y; wv[2] = w0.z; wv[3] = w0.w;
            if (TN == 8) {
                float4 w1 = *(const float4*)&Ws[k][64 + tc * 4];
                wv[4] = w1.x; wv[5] = w1.y; wv[6] = w1.z; wv[7] = w1.w;
            }
            #pragma unroll
            for (int i = 0; i < TM; i++)
                #pragma unroll
                for (int j = 0; j < TN; j++)
                    acc[i][j] = fmaf(a[i], wv[j], acc[i][j]);
        }
    }

    float bj[TN];
    #pragma unroll
    for (int j = 0; j < TN; j++) {
        int c = (TN == 8) ? ((j < 4) ? tc * 4 + j : 64 + tc * 4 + (j - 4)) : tc * 4 + j;
        bj[j] = BIAS ? __ldg(&bias[c]) : 0.f;
    }

    float csum[TN], csq[TN];
    #pragma unroll
    for (int j = 0; j < TN; j++) { csum[j] = 0.f; csq[j] = 0.f; }

    #pragma unroll
    for (int i = 0; i < TM; i++) {
        int gr = row0 + tr * TM + i;
        if (gr < nrows) {
            float h[TN];
            #pragma unroll
            for (int j = 0; j < TN; j++) h[j] = acc[i][j] + bj[j];
            float4 o0 = {h[0], h[1], h[2], h[3]};
            *(float4*)&out[(size_t)gr * MD + tc * 4] = o0;
            if (TN == 8) {
                float4 o1 = {h[4], h[5], h[6], h[7]};
                *(float4*)&out[(size_t)gr * MD + 64 + tc * 4] = o1;
            }
            if (STATS) {
                #pragma unroll
                for (int j = 0; j < TN; j++) { csum[j] += h[j]; csq[j] += h[j] * h[j]; }
            }
        }
    }

    if (STATS) {
        __syncthreads();
        #pragma unroll
        for (int j = 0; j < TN; j++) {
            int c = (TN == 8) ? ((j < 4) ? tc * 4 + j : 64 + tc * 4 + (j - 4)) : tc * 4 + j;
            atomicAdd(&s_sum[c], csum[j]);
            atomicAdd(&s_sq[c], csq[j]);
        }
        __syncthreads();
        if (tid < MD) {
            atomicAdd(&g_stats[tid], s_sum[tid]);
            atomicAdd(&g_stats[128 + tid], s_sq[tid]);
        }
    }
}

__global__ void k_zero_stats() { g_stats[threadIdx.x] = 0.f; }

__global__ void k_bnfin(const float* __restrict__ gamma,
                        const float* __restrict__ beta, int MD) {
    int c = threadIdx.x;
    if (c < MD) {
        float s = g_stats[c], q = g_stats[128 + c];
        float mean = s * (1.0f / NNODES);
        float var = q * (1.0f / NNODES) - mean * mean;
        float sc = __ldg(&gamma[c]) * rsqrtf(var + 1e-5f);
        g_ss[c] = sc;
        g_ss[128 + c] = fmaf(-mean, sc, __ldg(&beta[c]));
    }
}

// ---------------- launch ----------------
extern "C" void kernel_launch(void* const* d_in, const int* in_sizes, int n_in,
                              void* d_out, int out_size) {
    const float* x   = (const float*)d_in[0];
    const void*  ei  = d_in[1];
    const float* W1  = (const float*)d_in[2];
    const float* b1  = (const float*)d_in[3];
    const float* ga1 = (const float*)d_in[4];
    const float* be1 = (const float*)d_in[5];
    const float* W2  = (const float*)d_in[6];
    const float* b2  = (const float*)d_in[7];
    const float* ga2 = (const float*)d_in[8];
    const float* be2 = (const float*)d_in[9];
    const float* W3  = (const float*)d_in[10];
    const float* b3  = (const float*)d_in[11];
    float* out = (float*)d_out;

    int E = in_sizes[1] / 2;
    if (E > MAXE) E = MAXE;

    float *bufA, *bufB;
    cudaGetSymbolAddress((void**)&bufA, g_bufA);
    cudaGetSymbolAddress((void**)&bufB, g_bufB);

    // dtype detect + CSR build (parallel scan)
    k_detect<<<2, 1024>>>((const unsigned int*)ei);
    k_zero_cnt<<<(NNODES + 1023) / 1024, 1024>>>();
    k_hist<<<1024, 256>>>(ei, E);
    k_scan1<<<SCAN_NB, SCAN_BLK>>>();
    k_scan2<<<1, 128>>>();
    k_scan3<<<SCAN_NB, SCAN_BLK>>>();
    k_fill<<<1024, 256>>>(ei, E);

    const int aggBlocks = (NNODES * 32 + 255) / 256;
    const int gemmBlocks = (NNODES + 127) / 128;

    // layer 1: agg(x) -> bufA[N,64]; GEMM1 (+b1, stats) -> bufB[N,128]
    k_agg64<<<aggBlocks, 256>>>(x, bufA);
    k_zero_stats<<<1, 256>>>();
    k_gemm<64, 128, 8, false, true, true><<<gemmBlocks, 256>>>(bufA, W1, b1, bufB, NNODES);
    k_bnfin<<<1, 128>>>(ga1, be1, 128);

    // layer 2: agg(relu(BN1(h1))) -> bufA[N,128]; GEMM2 (+b2, stats) -> bufB[N,128]
    k_agg128_bn<<<aggBlocks, 256>>>(bufB, bufA);
    k_zero_stats<<<1, 256>>>();
    k_gemm<128, 128, 8, false, true, true><<<gemmBlocks, 256>>>(bufA, W2, b2, bufB, NNODES);
    k_bnfin<<<1, 128>>>(ga2, be2, 128);

    // layer 3 (reordered): t = relu(BN2(h2)) @ W3^T -> bufA[N,64]; agg(t)+b3 -> out
    k_gemm<128, 64, 4, true, false, false><<<gemmBlocks, 256>>>(bufB, W3, nullptr, bufA, NNODES);
    k_agg64_bias<<<aggBlocks, 256>>>(bufA, b3, out);
}

// round 4
// speedup vs baseline: 1.3005x; 1.1559x over previous
#include <cuda_runtime.h>
#include <cstddef>

#define NNODES 100000
#define MAXE   1600000
#define SCAN_BLK 1024
#define SCAN_NB  ((NNODES + SCAN_BLK - 1) / SCAN_BLK)   // 98

// ---------------- scratch (static device globals; no allocations) ----------------
__device__ __align__(16) float g_bufA[(size_t)NNODES * 128];
__device__ __align__(16) float g_bufB[(size_t)NNODES * 128];
__device__ int   g_cnt[NNODES];
__device__ int   g_wp[NNODES];
__device__ int   g_row_ptr[NNODES + 1];
__device__ int   g_col[MAXE];
__device__ unsigned long long g_blkp[SCAN_NB];
__device__ float g_invdeg[NNODES];
__device__ __align__(16) float g_stats[512];   // layer1: [0,256) ; layer2: [256,512)
__device__ __align__(16) float g_ss[256];      // [scale[128], shift[128]]
__device__ int   g_is64 = 1;                   // module-init; only 0 is ever written

// ---------------- init: zero counters/flags/stats + dtype detect ----------------
// int64 node ids < 2^31: every odd 32-bit word is 0. int32 data: odd words are
// random node ids -> essentially never all zero over 2048 samples. Only writes
// 0 -> deterministic across graph replays for fixed input.
__global__ void k_init(const unsigned int* __restrict__ w) {
    int i = blockIdx.x * blockDim.x + threadIdx.x;
    if (i < NNODES) g_cnt[i] = 0;
    if (i < SCAN_NB) g_blkp[i] = 0ull;
    if (i < 512) g_stats[i] = 0.f;
    if (i < 2048) {
        if (w[2 * i + 1] != 0u) g_is64 = 0;   // benign race: only writes 0
    }
}

// histogram of destination rows, reading edge_index directly (either dtype)
__global__ void k_hist(const void* __restrict__ ei, int E) {
    int is64 = g_is64;
    int i = blockIdx.x * blockDim.x + threadIdx.x;
    int stride = gridDim.x * blockDim.x;
    if (is64) {
        const long long* p = (const long long*)ei;
        for (; i < E; i += stride) atomicAdd(&g_cnt[(int)p[i]], 1);
    } else {
        const int* p = (const int*)ei;
        for (; i < E; i += stride) atomicAdd(&g_cnt[p[i]], 1);
    }
}

// ---------------- single-kernel decoupled scan over g_cnt ----------------
// Each block: tile scan, publish own aggregate (packed with flag), spin-read
// all predecessors' aggregates (all 98 blocks co-resident on 148 SMs -> safe),
// then write row_ptr / wp / invdeg.
__global__ void k_scan() {
    __shared__ int wsum[32];
    __shared__ int blk_off;
    int tid = threadIdx.x, lane = tid & 31, w = tid >> 5;
    int bid = blockIdx.x;
    if (tid == 0) blk_off = 0;

    int i = bid * SCAN_BLK + tid;
    int v = (i < NNODES) ? g_cnt[i] : 0;
    int s = v;
    #pragma unroll
    for (int o = 1; o < 32; o <<= 1) {
        int t = __shfl_up_sync(0xffffffffu, s, o);
        if (lane >= o) s += t;
    }
    if (lane == 31) wsum[w] = s;
    __syncthreads();
    if (w == 0) {
        int x = wsum[lane];
        int ss = x;
        #pragma unroll
        for (int o = 1; o < 32; o <<= 1) {
            int t = __shfl_up_sync(0xffffffffu, ss, o);
            if (lane >= o) ss += t;
        }
        wsum[lane] = ss - x;             // exclusive warp offsets
        if (lane == 31) {                // ss == block aggregate
            atomicExch(&g_blkp[bid], (((unsigned long long)(unsigned)ss) << 1) | 1ull);
        }
    }
    __syncthreads();

    if (tid < bid) {                     // gather predecessors' aggregates
        const volatile unsigned long long* p = &g_blkp[tid];
        unsigned long long pv;
        do { pv = *p; } while (!(pv & 1ull));
        atomicAdd(&blk_off, (int)(pv >> 1));
    }
    __syncthreads();

    int incl = s + wsum[w] + blk_off;
    if (i < NNODES) {
        g_row_ptr[i + 1] = incl;
        g_wp[i] = incl - v;
        g_invdeg[i] = 1.0f / ((float)v + 1e-6f);
        if (i == 0) g_row_ptr[0] = 0;
    }
}

// fill CSR columns, reading edge_index directly
__global__ void k_fill(const void* __restrict__ ei, int E) {
    int is64 = g_is64;
    int i = blockIdx.x * blockDim.x + threadIdx.x;
    int stride = gridDim.x * blockDim.x;
    if (is64) {
        const long long* p = (const long long*)ei;
        for (; i < E; i += stride) {
            int r = (int)p[i];
            int c = (int)p[E + i];
            int q = atomicAdd(&g_wp[r], 1);
            g_col[q] = c;
        }
    } else {
        const int* p = (const int*)ei;
        for (; i < E; i += stride) {
            int r = p[i];
            int c = p[E + i];
            int q = atomicAdd(&g_wp[r], 1);
            g_col[q] = c;
        }
    }
}

// ---------------- aggregation kernels (warp per node, 4-wide edge unroll) ------
__global__ void k_agg64(const float* __restrict__ src, float* __restrict__ dst) {
    int gw = (blockIdx.x * blockDim.x + threadIdx.x) >> 5;
    if (gw >= NNODES) return;
    int lane = threadIdx.x & 31;
    int beg = g_row_ptr[gw], end = g_row_ptr[gw + 1];
    float2 a0 = {0.f, 0.f}, a1 = {0.f, 0.f};
    const float2* s2 = (const float2*)src;
    int e = beg;
    for (; e + 3 < end; e += 4) {
        int c0 = __ldg(&g_col[e]),     c1 = __ldg(&g_col[e + 1]);
        int c2 = __ldg(&g_col[e + 2]), c3 = __ldg(&g_col[e + 3]);
        float2 v0 = __ldg(s2 + (size_t)c0 * 32 + lane);
        float2 v1 = __ldg(s2 + (size_t)c1 * 32 + lane);
        float2 v2 = __ldg(s2 + (size_t)c2 * 32 + lane);
        float2 v3 = __ldg(s2 + (size_t)c3 * 32 + lane);
        a0.x += v0.x; a0.y += v0.y;
        a1.x += v1.x; a1.y += v1.y;
        a0.x += v2.x; a0.y += v2.y;
        a1.x += v3.x; a1.y += v3.y;
    }
    for (; e < end; e++) {
        int c0 = __ldg(&g_col[e]);
        float2 v0 = __ldg(s2 + (size_t)c0 * 32 + lane);
        a0.x += v0.x; a0.y += v0.y;
    }
    float w = g_invdeg[gw];
    float2 r;
    r.x = (a0.x + a1.x) * w;
    r.y = (a0.y + a1.y) * w;
    ((float2*)dst)[(size_t)gw * 32 + lane] = r;
}

// gather h1 [N,128], apply BN(scale/shift)+relu on the fly, aggregate
__global__ void k_agg128_bn(const float* __restrict__ src, float* __restrict__ dst) {
    int gw = (blockIdx.x * blockDim.x + threadIdx.x) >> 5;
    if (gw >= NNODES) return;
    int lane = threadIdx.x & 31;
    float4 sc = *(const float4*)&g_ss[lane * 4];
    float4 sh = *(const float4*)&g_ss[128 + lane * 4];
    int beg = g_row_ptr[gw], end = g_row_ptr[gw + 1];
    float4 a0 = {0.f, 0.f, 0.f, 0.f}, a1 = {0.f, 0.f, 0.f, 0.f};
    const float4* s4 = (const float4*)src;
    int e = beg;
    for (; e + 3 < end; e += 4) {
        int c0 = __ldg(&g_col[e]),     c1 = __ldg(&g_col[e + 1]);
        int c2 = __ldg(&g_col[e + 2]), c3 = __ldg(&g_col[e + 3]);
        float4 v0 = __ldg(s4 + (size_t)c0 * 32 + lane);
        float4 v1 = __ldg(s4 + (size_t)c1 * 32 + lane);
        float4 v2 = __ldg(s4 + (size_t)c2 * 32 + lane);
        float4 v3 = __ldg(s4 + (size_t)c3 * 32 + lane);
        a0.x += fmaxf(fmaf(v0.x, sc.x, sh.x), 0.f);
        a0.y += fmaxf(fmaf(v0.y, sc.y, sh.y), 0.f);
        a0.z += fmaxf(fmaf(v0.z, sc.z, sh.z), 0.f);
        a0.w += fmaxf(fmaf(v0.w, sc.w, sh.w), 0.f);
        a1.x += fmaxf(fmaf(v1.x, sc.x, sh.x), 0.f);
        a1.y += fmaxf(fmaf(v1.y, sc.y, sh.y), 0.f);
        a1.z += fmaxf(fmaf(v1.z, sc.z, sh.z), 0.f);
        a1.w += fmaxf(fmaf(v1.w, sc.w, sh.w), 0.f);
        a0.x += fmaxf(fmaf(v2.x, sc.x, sh.x), 0.f);
        a0.y += fmaxf(fmaf(v2.y, sc.y, sh.y), 0.f);
        a0.z += fmaxf(fmaf(v2.z, sc.z, sh.z), 0.f);
        a0.w += fmaxf(fmaf(v2.w, sc.w, sh.w), 0.f);
        a1.x += fmaxf(fmaf(v3.x, sc.x, sh.x), 0.f);
        a1.y += fmaxf(fmaf(v3.y, sc.y, sh.y), 0.f);
        a1.z += fmaxf(fmaf(v3.z, sc.z, sh.z), 0.f);
        a1.w += fmaxf(fmaf(v3.w, sc.w, sh.w), 0.f);
    }
    for (; e < end; e++) {
        int c0 = __ldg(&g_col[e]);
        float4 v0 = __ldg(s4 + (size_t)c0 * 32 + lane);
        a0.x += fmaxf(fmaf(v0.x, sc.x, sh.x), 0.f);
        a0.y += fmaxf(fmaf(v0.y, sc.y, sh.y), 0.f);
        a0.z += fmaxf(fmaf(v0.z, sc.z, sh.z), 0.f);
        a0.w += fmaxf(fmaf(v0.w, sc.w, sh.w), 0.f);
    }
    float w = g_invdeg[gw];
    float4 r;
    r.x = (a0.x + a1.x) * w;
    r.y = (a0.y + a1.y) * w;
    r.z = (a0.z + a1.z) * w;
    r.w = (a0.w + a1.w) * w;
    ((float4*)dst)[(size_t)gw * 32 + lane] = r;
}

// final: aggregate t [N,64], add bias b3 -> d_out
__global__ void k_agg64_bias(const float* __restrict__ src,
                             const float* __restrict__ b3,
                             float* __restrict__ dst) {
    int gw = (blockIdx.x * blockDim.x + threadIdx.x) >> 5;
    if (gw >= NNODES) return;
    int lane = threadIdx.x & 31;
    float2 bb = __ldg((const float2*)b3 + lane);
    int beg = g_row_ptr[gw], end = g_row_ptr[gw + 1];
    float2 a0 = {0.f, 0.f}, a1 = {0.f, 0.f};
    const float2* s2 = (const float2*)src;
    int e = beg;
    for (; e + 3 < end; e += 4) {
        int c0 = __ldg(&g_col[e]),     c1 = __ldg(&g_col[e + 1]);
        int c2 = __ldg(&g_col[e + 2]), c3 = __ldg(&g_col[e + 3]);
        float2 v0 = __ldg(s2 + (size_t)c0 * 32 + lane);
        float2 v1 = __ldg(s2 + (size_t)c1 * 32 + lane);
        float2 v2 = __ldg(s2 + (size_t)c2 * 32 + lane);
        float2 v3 = __ldg(s2 + (size_t)c3 * 32 + lane);
        a0.x += v0.x; a0.y += v0.y;
        a1.x += v1.x; a1.y += v1.y;
        a0.x += v2.x; a0.y += v2.y;
        a1.x += v3.x; a1.y += v3.y;
    }
    for (; e < end; e++) {
        int c0 = __ldg(&g_col[e]);
        float2 v0 = __ldg(s2 + (size_t)c0 * 32 + lane);
        a0.x += v0.x; a0.y += v0.y;
    }
    float w = g_invdeg[gw];
    float2 r;
    r.x = fmaf(a0.x + a1.x, w, bb.x);
    r.y = fmaf(a0.y + a1.y, w, bb.y);
    ((float2*)dst)[(size_t)gw * 32 + lane] = r;
}

// ---------------- GEMM: out[n][m] = sum_k A[n][k]*W[m][k] (+bias), opt BN+relu on A,
// opt per-column sum/sumsq accumulation into g_stats[SOFF..] ----------------
template <int KD, int MD, int TN, bool BN_IN, bool STATS, bool BIAS, int SOFF>
__global__ void __launch_bounds__(256)
k_gemm(const float* __restrict__ A, const float* __restrict__ W,
       const float* __restrict__ bias, float* __restrict__ out, int nrows) {
    constexpr int KC = 16, BM = 128, TM = 8;
    __shared__ __align__(16) float As[KC][BM + 4];
    __shared__ __align__(16) float Ws[KC][MD];
    __shared__ float s_sum[128];
    __shared__ float s_sq[128];

    int tid = threadIdx.x;
    int tr = tid >> 4, tc = tid & 15;
    int row0 = blockIdx.x * BM;

    float acc[TM][TN];
    #pragma unroll
    for (int i = 0; i < TM; i++)
        #pragma unroll
        for (int j = 0; j < TN; j++) acc[i][j] = 0.f;

    if (STATS && tid < MD) { s_sum[tid] = 0.f; s_sq[tid] = 0.f; }

    for (int kc = 0; kc < KD; kc += KC) {
        __syncthreads();
        // A tile, stored transposed: As[k][r]
        for (int idx = tid; idx < BM * KC; idx += 256) {
            int k = idx & (KC - 1);
            int r = idx >> 4;
            int gr = row0 + r;
            float v = (gr < nrows) ? __ldg(&A[(size_t)gr * KD + kc + k]) : 0.f;
            if (BN_IN) {
                v = fmaxf(fmaf(v, __ldg(&g_ss[kc + k]), __ldg(&g_ss[128 + kc + k])), 0.f);
            }
            As[k][r] = v;
        }
        // W tile transposed: Ws[k][c] = W[c][kc+k]
        for (int idx = tid; idx < KC * MD; idx += 256) {
            int k = idx & (KC - 1);
            int c = idx >> 4;
            Ws[k][c] = __ldg(&W[(size_t)c * KD + kc + k]);
        }
        __syncthreads();

        #pragma unroll
        for (int k = 0; k < KC; k++) {
            float4 av0 = *(const float4*)&As[k][tr * TM];
            float4 av1 = *(const float4*)&As[k][tr * TM + 4];
            float a[TM] = {av0.x, av0.y, av0.z, av0.w, av1.x, av1.y, av1.z, av1.w};
            float wv[TN];
            float4 w0 = *(const float4*)&Ws[k][tc * 4];
            wv[0] = w0.x; wv[1] = w0.y; wv[2] = w0.z; wv[3] = w0.w;
            if (TN == 8) {
                float4 w1 = *(const float4*)&Ws[k][64 + tc * 4];
                wv[4] = w1.x; wv[5] = w1.y; wv[6] = w1.z; wv[7] = w1.w;
            }
            #pragma unroll
            for (int i = 0; i < TM; i++)
                #pragma unroll
                for (int j = 0; j < TN; j++)
                    acc[i][j] = fmaf(a[i], wv[j], acc[i][j]);
        }
    }

    float bj[TN];
    #pragma unroll
    for (int j = 0; j < TN; j++) {
        int c = (TN == 8) ? ((j < 4) ? tc * 4 + j : 64 + tc * 4 + (j - 4)) : tc * 4 + j;
        bj[j] = BIAS ? __ldg(&bias[c]) : 0.f;
    }

    float csum[TN], csq[TN];
    #pragma unroll
    for (int j = 0; j < TN; j++) { csum[j] = 0.f; csq[j] = 0.f; }

    #pragma unroll
    for (int i = 0; i < TM; i++) {
        int gr = row0 + tr * TM + i;
        if (gr < nrows) {
            float h[TN];
            #pragma unroll
            for (int j = 0; j < TN; j++) h[j] = acc[i][j] + bj[j];
            float4 o0 = {h[0], h[1], h[2], h[3]};
            *(float4*)&out[(size_t)gr * MD + tc * 4] = o0;
            if (TN == 8) {
                float4 o1 = {h[4], h[5], h[6], h[7]};
                *(float4*)&out[(size_t)gr * MD + 64 + tc * 4] = o1;
            }
            if (STATS) {
                #pragma unroll
                for (int j = 0; j < TN; j++) { csum[j] += h[j]; csq[j] += h[j] * h[j]; }
            }
        }
    }

    if (STATS) {
        __syncthreads();
        #pragma unroll
        for (int j = 0; j < TN; j++) {
            int c = (TN == 8) ? ((j < 4) ? tc * 4 + j : 64 + tc * 4 + (j - 4)) : tc * 4 + j;
            atomicAdd(&s_sum[c], csum[j]);
            atomicAdd(&s_sq[c], csq[j]);
        }
        __syncthreads();
        if (tid < MD) {
            atomicAdd(&g_stats[SOFF + tid], s_sum[tid]);
            atomicAdd(&g_stats[SOFF + 128 + tid], s_sq[tid]);
        }
    }
}

__global__ void k_bnfin(const float* __restrict__ gamma,
                        const float* __restrict__ beta, int soff) {
    int c = threadIdx.x;
    if (c < 128) {
        float s = g_stats[soff + c], q = g_stats[soff + 128 + c];
        float mean = s * (1.0f / NNODES);
        float var = q * (1.0f / NNODES) - mean * mean;
        float sc = __ldg(&gamma[c]) * rsqrtf(var + 1e-5f);
        g_ss[c] = sc;
        g_ss[128 + c] = fmaf(-mean, sc, __ldg(&beta[c]));
    }
}

// ---------------- launch ----------------
extern "C" void kernel_launch(void* const* d_in, const int* in_sizes, int n_in,
                              void* d_out, int out_size) {
    const float* x   = (const float*)d_in[0];
    const void*  ei  = d_in[1];
    const float* W1  = (const float*)d_in[2];
    const float* b1  = (const float*)d_in[3];
    const float* ga1 = (const float*)d_in[4];
    const float* be1 = (const float*)d_in[5];
    const float* W2  = (const float*)d_in[6];
    const float* b2  = (const float*)d_in[7];
    const float* ga2 = (const float*)d_in[8];
    const float* be2 = (const float*)d_in[9];
    const float* W3  = (const float*)d_in[10];
    const float* b3  = (const float*)d_in[11];
    float* out = (float*)d_out;

    int E = in_sizes[1] / 2;
    if (E > MAXE) E = MAXE;

    float *bufA, *bufB;
    cudaGetSymbolAddress((void**)&bufA, g_bufA);
    cudaGetSymbolAddress((void**)&bufB, g_bufB);

    // CSR build: 4 launches, so k_agg64 is launch #5 (ncu -s 5 profiles it)
    k_init<<<SCAN_NB, SCAN_BLK>>>((const unsigned int*)ei);
    k_hist<<<1024, 256>>>(ei, E);
    k_scan<<<SCAN_NB, SCAN_BLK>>>();
    k_fill<<<1024, 256>>>(ei, E);

    const int aggBlocks = (NNODES * 32 + 255) / 256;
    const int gemmBlocks = (NNODES + 127) / 128;

    // layer 1: agg(x) -> bufA[N,64]; GEMM1 (+b1, stats->0) -> bufB[N,128]
    k_agg64<<<aggBlocks, 256>>>(x, bufA);
    k_gemm<64, 128, 8, false, true, true, 0><<<gemmBlocks, 256>>>(bufA, W1, b1, bufB, NNODES);
    k_bnfin<<<1, 128>>>(ga1, be1, 0);

    // layer 2: agg(relu(BN1(h1))) -> bufA[N,128]; GEMM2 (+b2, stats->256) -> bufB[N,128]
    k_agg128_bn<<<aggBlocks, 256>>>(bufB, bufA);
    k_gemm<128, 128, 8, false, true, true, 256><<<gemmBlocks, 256>>>(bufA, W2, b2, bufB, NNODES);
    k_bnfin<<<1, 128>>>(ga2, be2, 256);

    // layer 3 (reordered): t = relu(BN2(h2)) @ W3^T -> bufA[N,64]; agg(t)+b3 -> out
    k_gemm<128, 64, 4, true, false, false, 0><<<gemmBlocks, 256>>>(bufB, W3, nullptr, bufA, NNODES);
    k_agg64_bias<<<aggBlocks, 256>>>(bufA, b3, out);
}